// round 1
// baseline (speedup 1.0000x reference)
#include <cuda_runtime.h>

#define KC 400
#define D 64
#define TPB 256

// packed fp32x2 FMA (sm_100+): d = a*b + d, elementwise .rn — bit-identical to 2x fmaf
__device__ __forceinline__ void fma2(unsigned long long &acc, unsigned long long a,
                                     unsigned long long b) {
    asm volatile("fma.rn.f32x2 %0, %1, %2, %0;" : "+l"(acc) : "l"(a), "l"(b));
}
__device__ __forceinline__ unsigned long long add2(unsigned long long a, unsigned long long b) {
    unsigned long long r;
    asm volatile("add.rn.f32x2 %0, %1, %2;" : "=l"(r) : "l"(a), "l"(b));
    return r;
}
__device__ __forceinline__ void unpack2(unsigned long long v, float &lo, float &hi) {
    asm volatile("mov.b64 {%0, %1}, %2;" : "=f"(lo), "=f"(hi) : "l"(v));
}

__global__ void __launch_bounds__(TPB)
vq_argmin_kernel(const float* __restrict__ x, const float* __restrict__ emb,
                 float* __restrict__ out, int nrows) {
    extern __shared__ float smem[];
    float* s_e    = smem;           // [KC*D] codes, row-major
    float* s_norm = smem + KC * D;  // [KC]   ||e_k||^2

    // stage codebook (coalesced, 100 float per thread)
    for (int i = threadIdx.x; i < KC * D; i += TPB) s_e[i] = emb[i];
    __syncthreads();
    for (int k = threadIdx.x; k < KC; k += TPB) {
        const float* e = s_e + k * D;
        float s = 0.f;
        #pragma unroll 16
        for (int d = 0; d < D; d++) s = fmaf(e[d], e[d], s);
        s_norm[k] = s;
    }
    __syncthreads();

    int row = blockIdx.x * TPB + threadIdx.x;
    if (row >= nrows) return;

    // row of x in registers, packed as 32 f32x2
    ulonglong2 xr[16];
    const ulonglong2* xp = reinterpret_cast<const ulonglong2*>(x + (size_t)row * D);
    #pragma unroll
    for (int i = 0; i < 16; i++) xr[i] = xp[i];

    const ulonglong2* se2 = reinterpret_cast<const ulonglong2*>(s_e);

    float best = 3.4e38f;
    int bestk = 0;

    #pragma unroll 2
    for (int k = 0; k < KC; k++) {
        // 4 independent packed accumulators for ILP
        unsigned long long a0 = 0ull, a1 = 0ull, a2 = 0ull, a3 = 0ull;
        const ulonglong2* e2 = se2 + k * 16;   // broadcast LDS (all lanes same addr)
        #pragma unroll
        for (int i = 0; i < 16; i += 2) {
            ulonglong2 ea = e2[i];
            ulonglong2 eb = e2[i + 1];
            fma2(a0, xr[i].x,     ea.x);
            fma2(a1, xr[i].y,     ea.y);
            fma2(a2, xr[i + 1].x, eb.x);
            fma2(a3, xr[i + 1].y, eb.y);
        }
        unsigned long long s01 = add2(a0, a1);
        unsigned long long s23 = add2(a2, a3);
        unsigned long long s   = add2(s01, s23);
        float lo, hi;
        unpack2(s, lo, hi);
        float dot = lo + hi;
        // score = ||e||^2 - 2*dot  (row-constant ||x||^2 dropped; argmin unchanged)
        float dist = fmaf(dot, -2.0f, s_norm[k]);
        if (dist < best) { best = dist; bestk = k; }   // strict <: first-min tie-break
    }

    // gather winning code from smem, write out
    const float4* cp = reinterpret_cast<const float4*>(s_e + bestk * D);
    float4* op = reinterpret_cast<float4*>(out + (size_t)row * D);
    #pragma unroll
    for (int i = 0; i < 16; i++) op[i] = cp[i];
}

extern "C" void kernel_launch(void* const* d_in, const int* in_sizes, int n_in,
                              void* d_out, int out_size) {
    const float* x   = (const float*)d_in[0];
    const float* emb = (const float*)d_in[1];
    float* out = (float*)d_out;

    int nrows = in_sizes[0] / D;   // 262144
    int smem_bytes = (KC * D + KC) * (int)sizeof(float);  // 104000 B

    // idempotent, executes immediately (not a stream op) — safe under graph capture
    cudaFuncSetAttribute(vq_argmin_kernel,
                         cudaFuncAttributeMaxDynamicSharedMemorySize, smem_bytes);

    int blocks = (nrows + TPB - 1) / TPB;
    vq_argmin_kernel<<<blocks, TPB, smem_bytes>>>(x, emb, out, nrows);
}

// round 2
// speedup vs baseline: 1.1720x; 1.1720x over previous
#include <cuda_runtime.h>

#define KC 400
#define D 64
#define TPB 256

// packed fp32x2 ops (sm_100+), elementwise .rn — bit-identical to 2x scalar fmaf/fadd.
// NOT volatile: pure arithmetic, let ptxas schedule freely.
__device__ __forceinline__ void fma2(unsigned long long &acc, unsigned long long a,
                                     unsigned long long b) {
    asm("fma.rn.f32x2 %0, %1, %2, %0;" : "+l"(acc) : "l"(a), "l"(b));
}
__device__ __forceinline__ unsigned long long add2(unsigned long long a, unsigned long long b) {
    unsigned long long r;
    asm("add.rn.f32x2 %0, %1, %2;" : "=l"(r) : "l"(a), "l"(b));
    return r;
}
__device__ __forceinline__ void unpack2(unsigned long long v, float &lo, float &hi) {
    asm("mov.b64 {%0, %1}, %2;" : "=f"(lo), "=f"(hi) : "l"(v));
}
__device__ __forceinline__ unsigned long long pack2(float lo, float hi) {
    unsigned long long r;
    asm("mov.b64 %0, {%1, %2};" : "=l"(r) : "f"(lo), "f"(hi));
    return r;
}

__global__ void __launch_bounds__(TPB, 2)
vq_argmin_kernel(const float* __restrict__ x, const float* __restrict__ emb,
                 float* __restrict__ out, int nrows) {
    extern __shared__ float smem[];
    float*              s_e  = smem;                 // [KC*D] codes, row-major
    unsigned long long* s_n2 = (unsigned long long*)(smem + KC * D);  // [KC] packed (-0.5*||e||^2, 0)

    // stage codebook (coalesced from L2)
    for (int i = threadIdx.x; i < KC * D; i += TPB) s_e[i] = emb[i];
    __syncthreads();
    for (int k = threadIdx.x; k < KC; k += TPB) {
        const float* e = s_e + k * D;
        float s = 0.f;
        #pragma unroll 16
        for (int d = 0; d < D; d++) s = fmaf(e[d], e[d], s);
        s_n2[k] = pack2(-0.5f * s, 0.0f);
    }
    __syncthreads();

    int row = blockIdx.x * TPB + threadIdx.x;
    if (row >= nrows) return;

    // row of x in registers: 32 packed f32x2
    ulonglong2 xr[16];
    const ulonglong2* xp = reinterpret_cast<const ulonglong2*>(x + (size_t)row * D);
    #pragma unroll
    for (int i = 0; i < 16; i++) xr[i] = xp[i];

    const ulonglong2* se2 = reinterpret_cast<const ulonglong2*>(s_e);

    // maximize score = x.e - 0.5*||e||^2  (== argmin of squared L2; ||x||^2 row-constant)
    float best = -3.4e38f;
    int bestk = 0;

    #pragma unroll 4
    for (int k = 0; k < KC; k++) {
        unsigned long long a0 = s_n2[k];          // broadcast LDS.64: (-0.5||e||^2, 0)
        unsigned long long a1 = 0ull, a2 = 0ull, a3 = 0ull;
        const ulonglong2* e2 = se2 + k * 16;      // broadcast LDS.128 x8
        #pragma unroll
        for (int i = 0; i < 16; i += 2) {
            ulonglong2 ea = e2[i];
            ulonglong2 eb = e2[i + 1];
            fma2(a0, xr[i].x,     ea.x);
            fma2(a1, xr[i].y,     ea.y);
            fma2(a2, xr[i + 1].x, eb.x);
            fma2(a3, xr[i + 1].y, eb.y);
        }
        unsigned long long s = add2(add2(a0, a1), add2(a2, a3));
        float lo, hi;
        unpack2(s, lo, hi);
        float score = lo + hi;
        if (score > best) { best = score; bestk = k; }  // strict >: first-max == first-min dist
    }

    // gather winning code from smem, write out
    const float4* cp = reinterpret_cast<const float4*>(s_e + bestk * D);
    float4* op = reinterpret_cast<float4*>(out + (size_t)row * D);
    #pragma unroll
    for (int i = 0; i < 16; i++) op[i] = cp[i];
}

extern "C" void kernel_launch(void* const* d_in, const int* in_sizes, int n_in,
                              void* d_out, int out_size) {
    const float* x   = (const float*)d_in[0];
    const float* emb = (const float*)d_in[1];
    float* out = (float*)d_out;

    int nrows = in_sizes[0] / D;   // 262144
    int smem_bytes = KC * D * (int)sizeof(float) + KC * (int)sizeof(unsigned long long); // 105600 B

    cudaFuncSetAttribute(vq_argmin_kernel,
                         cudaFuncAttributeMaxDynamicSharedMemorySize, smem_bytes);

    int blocks = (nrows + TPB - 1) / TPB;
    vq_argmin_kernel<<<blocks, TPB, smem_bytes>>>(x, emb, out, nrows);
}

// round 3
// speedup vs baseline: 1.4496x; 1.2368x over previous
#include <cuda_runtime.h>

#define KC 400
#define D 64
#define TPB 128
#define ROWS_PER_THREAD 2

// packed fp32x2 ops (sm_100+), elementwise .rn — bit-identical to 2x scalar fmaf/fadd.
__device__ __forceinline__ void fma2(unsigned long long &acc, unsigned long long a,
                                     unsigned long long b) {
    asm("fma.rn.f32x2 %0, %1, %2, %0;" : "+l"(acc) : "l"(a), "l"(b));
}
__device__ __forceinline__ unsigned long long add2(unsigned long long a, unsigned long long b) {
    unsigned long long r;
    asm("add.rn.f32x2 %0, %1, %2;" : "=l"(r) : "l"(a), "l"(b));
    return r;
}
__device__ __forceinline__ void unpack2(unsigned long long v, float &lo, float &hi) {
    asm("mov.b64 {%0, %1}, %2;" : "=f"(lo), "=f"(hi) : "l"(v));
}
__device__ __forceinline__ unsigned long long pack2(float lo, float hi) {
    unsigned long long r;
    asm("mov.b64 %0, {%1, %2};" : "=l"(r) : "f"(lo), "f"(hi));
    return r;
}

__global__ void __launch_bounds__(TPB, 2)
vq_argmin_kernel(const float* __restrict__ x, const float* __restrict__ emb,
                 float* __restrict__ out, int nrows) {
    extern __shared__ float smem[];
    float*              s_e  = smem;                                   // [KC*D] codes
    unsigned long long* s_n2 = (unsigned long long*)(smem + KC * D);   // [KC] packed (-0.5||e||^2, 0)

    // stage codebook (coalesced from L2)
    for (int i = threadIdx.x; i < KC * D; i += TPB) s_e[i] = emb[i];
    __syncthreads();
    for (int k = threadIdx.x; k < KC; k += TPB) {
        const float* e = s_e + k * D;
        float s = 0.f;
        #pragma unroll 16
        for (int d = 0; d < D; d++) s = fmaf(e[d], e[d], s);
        s_n2[k] = pack2(-0.5f * s, 0.0f);
    }
    __syncthreads();

    // two rows per thread, strided by TPB so warp LDG/STG pattern matches TR=1
    int row0 = blockIdx.x * (TPB * ROWS_PER_THREAD) + threadIdx.x;
    int row1 = row0 + TPB;
    if (row1 >= nrows) {   // full tail block handling (grid is exact for this shape)
        if (row0 >= nrows) return;
        row1 = row0;       // degenerate: duplicate work, same result
    }

    // both rows in registers: 16 ulonglong2 (= 64 floats) each
    ulonglong2 x0[16], x1[16];
    const ulonglong2* p0 = reinterpret_cast<const ulonglong2*>(x + (size_t)row0 * D);
    const ulonglong2* p1 = reinterpret_cast<const ulonglong2*>(x + (size_t)row1 * D);
    #pragma unroll
    for (int i = 0; i < 16; i++) { x0[i] = p0[i]; x1[i] = p1[i]; }

    const ulonglong2* se2 = reinterpret_cast<const ulonglong2*>(s_e);

    // maximize score = x.e - 0.5*||e||^2  (== argmin squared L2; ||x||^2 row-constant)
    float best0 = -3.4e38f, best1 = -3.4e38f;
    int bk0 = 0, bk1 = 0;

    #pragma unroll 2
    for (int k = 0; k < KC; k++) {
        unsigned long long n = s_n2[k];           // one broadcast LDS.64, reused by both rows
        unsigned long long a0 = n, a1 = 0ull;     // row0: 2 chains
        unsigned long long b0 = n, b1 = 0ull;     // row1: 2 chains
        const ulonglong2* e2 = se2 + k * 16;      // 8 broadcast LDS.128, each feeds 8 FFMA2
        #pragma unroll
        for (int i = 0; i < 16; i += 2) {
            ulonglong2 ea = e2[i];
            ulonglong2 eb = e2[i + 1];
            fma2(a0, x0[i].x, ea.x);     fma2(a1, x0[i].y, ea.y);
            fma2(b0, x1[i].x, ea.x);     fma2(b1, x1[i].y, ea.y);
            fma2(a0, x0[i + 1].x, eb.x); fma2(a1, x0[i + 1].y, eb.y);
            fma2(b0, x1[i + 1].x, eb.x); fma2(b1, x1[i + 1].y, eb.y);
        }
        unsigned long long sa = add2(a0, a1);
        unsigned long long sb = add2(b0, b1);
        float lo, hi;
        unpack2(sa, lo, hi);
        float sc0 = lo + hi;
        unpack2(sb, lo, hi);
        float sc1 = lo + hi;
        if (sc0 > best0) { best0 = sc0; bk0 = k; }   // strict >: first-max == jnp first-min
        if (sc1 > best1) { best1 = sc1; bk1 = k; }
    }

    // gather winning codes from smem, write out
    {
        const float4* cp = reinterpret_cast<const float4*>(s_e + bk0 * D);
        float4* op = reinterpret_cast<float4*>(out + (size_t)row0 * D);
        #pragma unroll
        for (int i = 0; i < 16; i++) op[i] = cp[i];
    }
    {
        const float4* cp = reinterpret_cast<const float4*>(s_e + bk1 * D);
        float4* op = reinterpret_cast<float4*>(out + (size_t)row1 * D);
        #pragma unroll
        for (int i = 0; i < 16; i++) op[i] = cp[i];
    }
}

extern "C" void kernel_launch(void* const* d_in, const int* in_sizes, int n_in,
                              void* d_out, int out_size) {
    const float* x   = (const float*)d_in[0];
    const float* emb = (const float*)d_in[1];
    float* out = (float*)d_out;

    int nrows = in_sizes[0] / D;   // 262144
    int smem_bytes = KC * D * (int)sizeof(float) + KC * (int)sizeof(unsigned long long); // 105600 B

    cudaFuncSetAttribute(vq_argmin_kernel,
                         cudaFuncAttributeMaxDynamicSharedMemorySize, smem_bytes);

    int rows_per_block = TPB * ROWS_PER_THREAD;
    int blocks = (nrows + rows_per_block - 1) / rows_per_block;   // 1024
    vq_argmin_kernel<<<blocks, TPB, smem_bytes>>>(x, emb, out, nrows);
}